// round 8
// baseline (speedup 1.0000x reference)
#include <cuda_runtime.h>
#include <math.h>
#include <stdint.h>

// ---------------------------------------------------------------------------
// CfC / AutoNCP decoder, wavefront-pipelined, fp32x2 packed-FMA inner product.
//   layer l at wavefront s computes t = s - l  (independent across layers)
//   Cell math per layer:
//     xc = [input, h];  ff1 = tanh(xc W1m^T + b1); ff2 = tanh(xc W2m^T + b2)
//     ti = sigmoid(xc (Wa+Wb)^T + (ba+bb));  h' = ff1 + ti*(ff2-ff1)
//   predictions = motor @ Wfc^T + bfc ; hn = concat(final h)
// Weights are repacked row-padded (stride KP = roundup(K,4)) so every 16B
// cp.async source chunk is 16B-aligned.
// ---------------------------------------------------------------------------

#define BB   512
#define TT   128
#define IDIM 512
#define OUTD 128

#define N0 538
#define N1 358
#define N2 128
#define K0 (IDIM + N0)   // 1050
#define K1 (N0 + N1)     // 896
#define K2 (N1 + N2)     // 486

// padded row strides (multiples of 4 floats -> 16B-aligned rows)
#define KP0 1052
#define KP1 896
#define KP2 488

#define PSZ0 (N0 * KP0)
#define PSZ1 (N1 * KP1)
#define PSZ2 (N2 * KP2)
#define PWOFF1 (PSZ0)
#define PWOFF2 (PSZ0 + PSZ1)
#define PTOT   (PSZ0 + PSZ1 + PSZ2)

#define OFFH0 0
#define OFFH1 (BB * N0)
#define OFFH2 (BB * (N0 + N1))
#define HTOT  (BB * 1024)

// Block partition of the fused wavefront grid
#define BLK_L0 272            // 17 col-tiles x 16 row-tiles (BM=32)
#define BLK_L1 192            // 12 x 16 (BM=32)
#define BLK_L2 128            //  4 x 32 (BM=16)
#define BLK_TOT (BLK_L0 + BLK_L1 + BLK_L2)   // 592

// Scratch (static device globals — no runtime allocation)
__device__ __align__(16) float gW1m[PTOT];   // Wff1 * mask  (row-padded)
__device__ __align__(16) float gW2m[PTOT];   // Wff2 * mask  (row-padded)
__device__ __align__(16) float gWab[PTOT];   // Wta + Wtb    (row-padded)
__device__ __align__(16) float gH[2][HTOT];  // wavefront-parity double buffer

// ---------------------------------------------------------------------------
// Precompute into row-padded layout; pad region zero-filled.
// ---------------------------------------------------------------------------
__global__ void prep_kernel(
    const float* __restrict__ W1_0, const float* __restrict__ W2_0,
    const float* __restrict__ Wa_0, const float* __restrict__ Wb_0, const float* __restrict__ m0,
    const float* __restrict__ W1_1, const float* __restrict__ W2_1,
    const float* __restrict__ Wa_1, const float* __restrict__ Wb_1, const float* __restrict__ m1,
    const float* __restrict__ W1_2, const float* __restrict__ W2_2,
    const float* __restrict__ Wa_2, const float* __restrict__ Wb_2, const float* __restrict__ m2)
{
    for (int i = blockIdx.x * blockDim.x + threadIdx.x; i < PTOT; i += gridDim.x * blockDim.x) {
        const float *W1, *W2, *Wa, *Wb, *m;
        int j, K, KP;
        if (i < PWOFF1)      { W1 = W1_0; W2 = W2_0; Wa = Wa_0; Wb = Wb_0; m = m0; j = i;          K = K0; KP = KP0; }
        else if (i < PWOFF2) { W1 = W1_1; W2 = W2_1; Wa = Wa_1; Wb = Wb_1; m = m1; j = i - PWOFF1; K = K1; KP = KP1; }
        else                 { W1 = W1_2; W2 = W2_2; Wa = Wa_2; Wb = Wb_2; m = m2; j = i - PWOFF2; K = K2; KP = KP2; }
        int row = j / KP;
        int k   = j - row * KP;
        float v1 = 0.f, v2 = 0.f, vab = 0.f;
        if (k < K) {
            int src = row * K + k;
            float mm = m[src];
            v1  = W1[src] * mm;
            v2  = W2[src] * mm;
            vab = Wa[src] + Wb[src];
        }
        gW1m[i] = v1;
        gW2m[i] = v2;
        gWab[i] = vab;
    }
}

// h0 -> per-layer contiguous state, written to BOTH parities (first read per
// layer happens at wavefront s = l, parity (l-1)&1).
__global__ void init_h_kernel(const float* __restrict__ h0)
{
    for (int idx = blockIdx.x * blockDim.x + threadIdx.x; idx < HTOT; idx += gridDim.x * blockDim.x) {
        int b = idx >> 10;
        int c = idx & 1023;
        float v = h0[idx];
        int off;
        if (c < N0)           off = OFFH0 + b * N0 + c;
        else if (c < N0 + N1) off = OFFH1 + b * N1 + (c - N0);
        else                  off = OFFH2 + b * N2 + (c - N0 - N1);
        gH[0][off] = v;
        gH[1][off] = v;
    }
}

// final h: layer0 @ s=127 -> gH[1]; layer1 @ s=128 -> gH[0]; layer2 @ s=129 -> gH[1]
__global__ void copy_hn_kernel(float* __restrict__ hn)
{
    for (int idx = blockIdx.x * blockDim.x + threadIdx.x; idx < HTOT; idx += gridDim.x * blockDim.x) {
        int b = idx >> 10;
        int c = idx & 1023;
        float v;
        if (c < N0)           v = gH[1][OFFH0 + b * N0 + c];
        else if (c < N0 + N1) v = gH[0][OFFH1 + b * N1 + (c - N0)];
        else                  v = gH[1][OFFH2 + b * N2 + (c - N0 - N1)];
        hn[idx] = v;
    }
}

// ---------------------------------------------------------------------------
// cp.async + fp32x2 helpers
// ---------------------------------------------------------------------------
__device__ __forceinline__ void cp4(void* dst_smem, const float* src, bool pred)
{
    uint32_t d = (uint32_t)__cvta_generic_to_shared(dst_smem);
    const float* s = pred ? src : (const float*)gW1m;   // safe aligned address when masked
    int sz = pred ? 4 : 0;                               // 0 -> zero-fill 4 bytes
    asm volatile("cp.async.ca.shared.global [%0], [%1], 4, %2;\n"
                 :: "r"(d), "l"(s), "r"(sz) : "memory");
}
__device__ __forceinline__ void cp16(void* dst_smem, const float* src, bool pred)
{
    uint32_t d = (uint32_t)__cvta_generic_to_shared(dst_smem);
    const float* s = pred ? src : (const float*)gW1m;   // gW1m is 16B-aligned
    int sz = pred ? 16 : 0;                              // 0 -> zero-fill 16 bytes
    asm volatile("cp.async.cg.shared.global [%0], [%1], 16, %2;\n"
                 :: "r"(d), "l"(s), "r"(sz) : "memory");
}
__device__ __forceinline__ void cp_commit() { asm volatile("cp.async.commit_group;\n" ::: "memory"); }
template <int N>
__device__ __forceinline__ void cp_wait() { asm volatile("cp.async.wait_group %0;\n" :: "n"(N) : "memory"); }

// packed fp32x2 FMA: d = a * b + c  (elementwise on the two fp32 halves)
__device__ __forceinline__ unsigned long long ffma2(
    unsigned long long a, unsigned long long b, unsigned long long c)
{
    unsigned long long d;
    asm("fma.rn.f32x2 %0, %1, %2, %3;" : "=l"(d) : "l"(a), "l"(b), "l"(c));
    return d;
}
// broadcast one fp32 into both halves of a b64 pair
__device__ __forceinline__ unsigned long long pack2(float x)
{
    unsigned long long d;
    asm("mov.b64 %0, {%1, %1};" : "=l"(d) : "f"(x));
    return d;
}
__device__ __forceinline__ float lo32(unsigned long long v) { return __uint_as_float((unsigned)v); }
__device__ __forceinline__ float hi32(unsigned long long v) { return __uint_as_float((unsigned)(v >> 32)); }

// smem tile strides (floats); both give 16B-aligned rows (36*4 = 144 B)
#define APAD 36     // As[k][row]
#define WPAD 36     // Ws[mat][col][k]

// ---------------------------------------------------------------------------
// Fused CfC cell body (templated per layer). 128 threads.
//   BN = 32 cols, BK = 32, BM = 4*TM rows.  lane = col, grp (0..3) = row group.
//   2-stage cp.async pipeline; 3 GEMMs share the A tile; fp32x2 inner product.
//   Smem:
//     As[st][k][row]       : A, k-major; compute reads are 16B row-pairs,
//                            warp-broadcast (lane-uniform address).
//     Ws[st][mat][col][k]  : W, k contiguous -> 16B cp.async from global,
//                            float4-per-4k LDS on compute, conflict-free.
// ---------------------------------------------------------------------------
template <int L>
__device__ __forceinline__ void cell_body(
    int bidx, int t, int wp,
    const float* __restrict__ x,
    const float* __restrict__ b1, const float* __restrict__ b2,
    const float* __restrict__ ba, const float* __restrict__ bb,
    float* __restrict__ out,
    float (*As)[32][APAD], float (*Ws)[3][32][WPAD])
{
    constexpr int n      = (L == 0) ? N0 : (L == 1) ? N1 : N2;
    constexpr int in_dim = (L == 0) ? IDIM : (L == 1) ? N0 : N1;
    constexpr int K      = in_dim + n;
    constexpr int KP     = (L == 0) ? KP0 : (L == 1) ? KP1 : KP2;
    constexpr int COLT   = (L == 0) ? 17 : (L == 1) ? 12 : 4;
    constexpr int TM     = (L == 2) ? 4 : 8;
    constexpr int BM     = TM * 4;
    constexpr int NP     = TM / 2;              // fp32x2 row-pairs per thread
    constexpr int NT     = (K + 31) / 32;
    constexpr int pwoff  = (L == 0) ? 0 : (L == 1) ? PWOFF1 : PWOFF2;
    constexpr int hoff   = (L == 0) ? OFFH0 : (L == 1) ? OFFH1 : OFFH2;
    constexpr int poff   = (L == 1) ? OFFH0 : (L == 2) ? OFFH1 : 0;

    const float* prevbuf = gH[wp ^ 1];
    const float* inA = (L == 0) ? (x + (size_t)t * IDIM) : (prevbuf + poff);
    const int    ldA = (L == 0) ? (TT * IDIM) : in_dim;
    const float* hcur = prevbuf + hoff;
    float*       hout = gH[wp] + hoff;

    const int tid  = threadIdx.x;
    const int lane = tid & 31;
    const int grp  = tid >> 5;
    const int rowBase = (bidx / COLT) * BM;
    const int colBase = (bidx % COLT) * 32;

    // per-thread source bases
    const float* pX = inA  + (size_t)(rowBase + grp * TM) * ldA + lane;  // + i*ldA + kt*32
    const float* pH = hcur + (size_t)(rowBase + grp * TM) * n + lane;    // + i*n + (kt*32 - in_dim)
    const int j = colBase + lane;
    const bool jok = (j < n);
    const size_t jo = (size_t)(jok ? j : 0) * KP + grp * 4;              // 16B-aligned row base
    const float* pW0 = gW1m + pwoff + jo;
    const float* pW1 = gW2m + pwoff + jo;
    const float* pW2 = gWab + pwoff + jo;

    unsigned long long acc[3][NP];
#pragma unroll
    for (int m = 0; m < 3; m++)
#pragma unroll
        for (int p = 0; p < NP; p++) acc[m][p] = 0ull;

    // ---- tile issue ----
    auto issue = [&](int kt, int st) {
        const int k0 = kt * 32;
        const int gk = k0 + lane;
        const bool kin = (gk < K);
        const bool inx = (gk < in_dim);
        // A: rows grp*TM + i at k = lane (4B cp.async, exact tail masking)
#pragma unroll
        for (int i = 0; i < TM; i++) {
            const float* src = inx ? (pX + i * ldA + k0)
                                   : (pH + i * n + (k0 - in_dim));
            cp4(&As[st][lane][grp * TM + i], src, kin);
        }
        // W: col j, k-chunks grp*4 and grp*4+16 (16B-aligned cp.async).
        // A chunk starting below K ends at <= KP (zero-padded), so in-bounds.
#pragma unroll
        for (int half = 0; half < 2; half++) {
            const int kc = grp * 4 + half * 16;
            const bool p = jok && (k0 + kc < K);
            cp16(&Ws[st][0][lane][kc], pW0 + k0 + half * 16, p);
            cp16(&Ws[st][1][lane][kc], pW1 + k0 + half * 16, p);
            cp16(&Ws[st][2][lane][kc], pW2 + k0 + half * 16, p);
        }
    };

    issue(0, 0);
    cp_commit();

    for (int kt = 0; kt < NT; kt++) {
        const int st = kt & 1;
        if (kt + 1 < NT) {
            issue(kt + 1, st ^ 1);
            cp_commit();
            cp_wait<1>();
        } else {
            cp_wait<0>();
        }
        __syncthreads();

#pragma unroll
        for (int k4 = 0; k4 < 8; k4++) {
            const float4 w0v = *reinterpret_cast<const float4*>(&Ws[st][0][lane][k4 * 4]);
            const float4 w1v = *reinterpret_cast<const float4*>(&Ws[st][1][lane][k4 * 4]);
            const float4 w2v = *reinterpret_cast<const float4*>(&Ws[st][2][lane][k4 * 4]);
#pragma unroll
            for (int kk = 0; kk < 4; kk++) {
                const int k = k4 * 4 + kk;
                // row-pairs for this thread (broadcast across warp)
                unsigned long long av[NP];
                const ulonglong2* ap =
                    reinterpret_cast<const ulonglong2*>(&As[st][k][grp * TM]);
#pragma unroll
                for (int q = 0; q < NP / 2; q++) {
                    ulonglong2 tq = ap[q];
                    av[2 * q]     = tq.x;
                    av[2 * q + 1] = tq.y;
                }
                const float w0f = (kk == 0) ? w0v.x : (kk == 1) ? w0v.y : (kk == 2) ? w0v.z : w0v.w;
                const float w1f = (kk == 0) ? w1v.x : (kk == 1) ? w1v.y : (kk == 2) ? w1v.z : w1v.w;
                const float w2f = (kk == 0) ? w2v.x : (kk == 1) ? w2v.y : (kk == 2) ? w2v.z : w2v.w;
                const unsigned long long w0 = pack2(w0f);
                const unsigned long long w1 = pack2(w1f);
                const unsigned long long w2 = pack2(w2f);
#pragma unroll
                for (int p = 0; p < NP; p++) {
                    acc[0][p] = ffma2(av[p], w0, acc[0][p]);
                    acc[1][p] = ffma2(av[p], w1, acc[1][p]);
                    acc[2][p] = ffma2(av[p], w2, acc[2][p]);
                }
            }
        }
        __syncthreads();
    }

    // ---- fused CfC epilogue ----
    if (jok) {
        const float vb1 = b1[j], vb2 = b2[j], vbs = ba[j] + bb[j];
#pragma unroll
        for (int p = 0; p < NP; p++) {
#pragma unroll
            for (int hl = 0; hl < 2; hl++) {
                const int gr = rowBase + grp * TM + 2 * p + hl;
                const float s1 = hl ? hi32(acc[0][p]) : lo32(acc[0][p]);
                const float s2 = hl ? hi32(acc[1][p]) : lo32(acc[1][p]);
                const float st_ = hl ? hi32(acc[2][p]) : lo32(acc[2][p]);
                const float f1 = tanhf(s1 + vb1);
                const float f2 = tanhf(s2 + vb2);
                const float ti = 1.f / (1.f + expf(-(st_ + vbs)));
                const float hv = f1 + ti * (f2 - f1);
                hout[(size_t)gr * n + j] = hv;
                if (L == 2) out[(size_t)gr * (TT * OUTD) + (size_t)t * OUTD + j] = hv;
            }
        }
    }
}

// ---------------------------------------------------------------------------
// One wavefront: layer l active when 0 <= s-l < 128.
// ---------------------------------------------------------------------------
__global__ __launch_bounds__(128, 4) void wave_kernel(
    int s, const float* __restrict__ x,
    const float* __restrict__ b1_0, const float* __restrict__ b2_0,
    const float* __restrict__ ba_0, const float* __restrict__ bb_0,
    const float* __restrict__ b1_1, const float* __restrict__ b2_1,
    const float* __restrict__ ba_1, const float* __restrict__ bb_1,
    const float* __restrict__ b1_2, const float* __restrict__ b2_2,
    const float* __restrict__ ba_2, const float* __restrict__ bb_2,
    float* __restrict__ out)
{
    __shared__ float As[2][32][APAD];
    __shared__ float Ws[2][3][32][WPAD];

    const int bx = blockIdx.x;
    const int wp = s & 1;

    if (bx < BLK_L0) {
        if (s < TT)
            cell_body<0>(bx, s, wp, x, b1_0, b2_0, ba_0, bb_0, nullptr, As, Ws);
    } else if (bx < BLK_L0 + BLK_L1) {
        int t = s - 1;
        if (t >= 0 && t < TT)
            cell_body<1>(bx - BLK_L0, t, wp, x, b1_1, b2_1, ba_1, bb_1, nullptr, As, Ws);
    } else {
        int t = s - 2;
        if (t >= 0 && t < TT)
            cell_body<2>(bx - BLK_L0 - BLK_L1, t, wp, x, b1_2, b2_2, ba_2, bb_2, out, As, Ws);
    }
}

// ---------------------------------------------------------------------------
// Final FC, in-place on d_out predictions region.
// ---------------------------------------------------------------------------
__global__ __launch_bounds__(256) void fc_kernel(float* __restrict__ pred,
                                                 const float* __restrict__ Wfc,
                                                 const float* __restrict__ bfc)
{
    __shared__ float As[64][129];
    const int tid  = threadIdx.x;
    const int lane = tid & 31;
    const int wrp  = tid >> 5;
    float* base = pred + (size_t)blockIdx.x * 64 * OUTD;

    for (int e = tid; e < 64 * OUTD; e += 256)
        As[e >> 7][e & 127] = base[e];
    __syncthreads();

    for (int jj = 0; jj < 16; jj++) {
        int j = jj * 8 + wrp;
        float acc0 = bfc[j], acc1 = bfc[j];
        const float* wr = Wfc + j * OUTD;
#pragma unroll 8
        for (int k = 0; k < OUTD; k++) {
            float wv = wr[k];
            acc0 += As[lane][k] * wv;
            acc1 += As[lane + 32][k] * wv;
        }
        base[lane * OUTD + j]        = acc0;
        base[(lane + 32) * OUTD + j] = acc1;
    }
}

// ---------------------------------------------------------------------------
extern "C" void kernel_launch(void* const* d_in, const int* in_sizes, int n_in,
                              void* d_out, int out_size)
{
    const float* x    = (const float*)d_in[0];
    const float* h0   = (const float*)d_in[1];

    const float* mask0 = (const float*)d_in[2];
    const float* W1_0  = (const float*)d_in[3];
    const float* W2_0  = (const float*)d_in[4];
    const float* Wa_0  = (const float*)d_in[5];
    const float* Wb_0  = (const float*)d_in[6];
    const float* b1_0  = (const float*)d_in[7];
    const float* b2_0  = (const float*)d_in[8];
    const float* ba_0  = (const float*)d_in[9];
    const float* bb_0  = (const float*)d_in[10];

    const float* mask1 = (const float*)d_in[11];
    const float* W1_1  = (const float*)d_in[12];
    const float* W2_1  = (const float*)d_in[13];
    const float* Wa_1  = (const float*)d_in[14];
    const float* Wb_1  = (const float*)d_in[15];
    const float* b1_1  = (const float*)d_in[16];
    const float* b2_1  = (const float*)d_in[17];
    const float* ba_1  = (const float*)d_in[18];
    const float* bb_1  = (const float*)d_in[19];

    const float* mask2 = (const float*)d_in[20];
    const float* W1_2  = (const float*)d_in[21];
    const float* W2_2  = (const float*)d_in[22];
    const float* Wa_2  = (const float*)d_in[23];
    const float* Wb_2  = (const float*)d_in[24];
    const float* b1_2  = (const float*)d_in[25];
    const float* b2_2  = (const float*)d_in[26];
    const float* ba_2  = (const float*)d_in[27];
    const float* bb_2  = (const float*)d_in[28];

    const float* Wfc  = (const float*)d_in[29];
    const float* bfc  = (const float*)d_in[30];

    float* out = (float*)d_out;

    prep_kernel<<<1024, 256>>>(W1_0, W2_0, Wa_0, Wb_0, mask0,
                               W1_1, W2_1, Wa_1, Wb_1, mask1,
                               W1_2, W2_2, Wa_2, Wb_2, mask2);
    init_h_kernel<<<1024, 256>>>(h0);

    // Wavefront sweep: s = 0 .. 129 (layer l computes t = s - l)
    for (int s = 0; s < TT + 2; s++) {
        wave_kernel<<<BLK_TOT, 128>>>(s, x,
                                      b1_0, b2_0, ba_0, bb_0,
                                      b1_1, b2_1, ba_1, bb_1,
                                      b1_2, b2_2, ba_2, bb_2,
                                      out);
    }

    // predictions = motor @ Wfc^T + bfc (in place)
    fc_kernel<<<(BB * TT) / 64, 256>>>(out, Wfc, bfc);

    if (out_size >= BB * TT * OUTD + BB * 1024)
        copy_hn_kernel<<<512, 256>>>(out + (size_t)BB * TT * OUTD);
}

// round 9
// speedup vs baseline: 2.6878x; 2.6878x over previous
#include <cuda_runtime.h>
#include <cuda_bf16.h>
#include <math.h>
#include <stdint.h>

// ---------------------------------------------------------------------------
// CfC / AutoNCP decoder — wavefront-pipelined, tensor-core (mma.sync bf16)
// with hi/lo split for fp32-grade accuracy.
//
//   layer l at wavefront s computes t = s - l  (independent across layers)
//   Cell: xc = [h, input] (REORDERED, h padded to n4);  per output j:
//     ff1 = tanh(xc.W1m^T + b1); ff2 = tanh(xc.W2m^T + b2)
//     ti  = sigmoid(xc.(Wa+Wb)^T + ba + bb);  h' = ff1 + ti*(ff2-ff1)
//   GEMMs run as mma.sync.m16n8k16.bf16 with 3-way split:
//     D = Ahi*Bhi + Ahi*Blo + Alo*Bhi   (lo*lo dropped, ~2^-16 rel)
// ---------------------------------------------------------------------------

#define BB   512
#define TT   128
#define IDIM 512
#define OUTD 128

#define N0 538
#define N1 358
#define N2 128

// padded h widths (multiples of 8) and reordered K' = n4 + in_dim
#define NP0 544
#define NP1 360
#define NP2P 128
// k-tiles of 32 per layer:  K'0=1056(33), K'1=898->29 tiles, K'2=486->16 tiles
#define NT0 33
#define NT1 29
#define NT2 16
#define KW0 (NT0*32)   // 1056 words/row in packed weight layout
#define KW1 (NT1*32)   // 928
#define KW2 (NT2*32)   // 512

#define QS0 (N0*KW0)   // 568128
#define QS1 (N1*KW1)   // 332224
#define QS2 (N2*KW2)   // 65536
#define QOFF1 (QS0)
#define QOFF2 (QS0+QS1)
#define QTOT  (QS0+QS1+QS2)

#define OFFH0 0
#define OFFH1 (BB*NP0)
#define OFFH2 (BB*(NP0+NP1))
#define HTOTP (BB*(NP0+NP1+NP2P) + 1024)

// wavefront grid partition (BM=64, BN=16)
#define BLK_L0 272    // 34 col-tiles x 8 row-tiles
#define BLK_L1 184    // 23 x 8
#define BLK_L2 64     //  8 x 8
#define BLK_TOT (BLK_L0 + BLK_L1 + BLK_L2)   // 520

// Static device scratch (no runtime allocation).
// Packed weights: per row j, per k-pair p: word 2p = bf16x2{hi(2p),hi(2p+1)},
// word 2p+1 = bf16x2{lo(2p),lo(2p+1)}.  Row stride = KW words.
__device__ __align__(16) uint32_t gWq1[QTOT];
__device__ __align__(16) uint32_t gWq2[QTOT];
__device__ __align__(16) uint32_t gWqab[QTOT];
__device__ __align__(16) float gH[2][HTOTP];   // parity double buffer, padded rows

// ---------------------------------------------------------------------------
// helpers
// ---------------------------------------------------------------------------
__device__ __forceinline__ int remap_k(int kp, int n, int n4, int in_dim)
{
    // reordered xc = [h(padded n4), input(in_dim)] -> original col index or -1
    if (kp < n4) return (kp < n) ? (in_dim + kp) : -1;
    int ks = kp - n4;
    return (ks < in_dim) ? ks : -1;
}

__device__ __forceinline__ uint32_t pack_sel(float f0, float f1, int isLo)
{
    __nv_bfloat16 h0 = __float2bfloat16_rn(f0);
    __nv_bfloat16 h1 = __float2bfloat16_rn(f1);
    if (isLo) {
        h0 = __float2bfloat16_rn(f0 - __bfloat162float(h0));
        h1 = __float2bfloat16_rn(f1 - __bfloat162float(h1));
    }
    return ((uint32_t)__bfloat16_as_ushort(h1) << 16) | (uint32_t)__bfloat16_as_ushort(h0);
}

__device__ __forceinline__ void split2(float f0, float f1, uint32_t& hi, uint32_t& lo)
{
    __nv_bfloat16 h0 = __float2bfloat16_rn(f0);
    __nv_bfloat16 h1 = __float2bfloat16_rn(f1);
    float r0 = f0 - __bfloat162float(h0);
    float r1 = f1 - __bfloat162float(h1);
    __nv_bfloat16 l0 = __float2bfloat16_rn(r0);
    __nv_bfloat16 l1 = __float2bfloat16_rn(r1);
    hi = ((uint32_t)__bfloat16_as_ushort(h1) << 16) | (uint32_t)__bfloat16_as_ushort(h0);
    lo = ((uint32_t)__bfloat16_as_ushort(l1) << 16) | (uint32_t)__bfloat16_as_ushort(l0);
}

__device__ __forceinline__ void mma16816(float* c, const uint32_t* a, uint32_t b0, uint32_t b1)
{
    asm volatile(
        "mma.sync.aligned.m16n8k16.row.col.f32.bf16.bf16.f32 "
        "{%0,%1,%2,%3}, {%4,%5,%6,%7}, {%8,%9}, {%0,%1,%2,%3};\n"
        : "+f"(c[0]), "+f"(c[1]), "+f"(c[2]), "+f"(c[3])
        : "r"(a[0]), "r"(a[1]), "r"(a[2]), "r"(a[3]), "r"(b0), "r"(b1));
}

__device__ __forceinline__ void cp16u(void* dst, const void* src)
{
    uint32_t d = (uint32_t)__cvta_generic_to_shared(dst);
    asm volatile("cp.async.cg.shared.global [%0], [%1], 16;\n" :: "r"(d), "l"(src) : "memory");
}
__device__ __forceinline__ void cp16p(void* dst, const void* src, bool pred)
{
    uint32_t d = (uint32_t)__cvta_generic_to_shared(dst);
    const void* s = pred ? src : (const void*)gWq1;   // 16B-aligned safe address
    int sz = pred ? 16 : 0;                            // 0 -> zero-fill 16B
    asm volatile("cp.async.cg.shared.global [%0], [%1], 16, %2;\n"
                 :: "r"(d), "l"(s), "r"(sz) : "memory");
}
__device__ __forceinline__ void cp_commit() { asm volatile("cp.async.commit_group;\n" ::: "memory"); }
template <int N>
__device__ __forceinline__ void cp_wait() { asm volatile("cp.async.wait_group %0;\n" :: "n"(N) : "memory"); }

// ---------------------------------------------------------------------------
// prep: build packed bf16 hi/lo weights (masked / summed, reordered, padded)
// ---------------------------------------------------------------------------
__global__ void prep_kernel(
    const float* __restrict__ W1_0, const float* __restrict__ W2_0,
    const float* __restrict__ Wa_0, const float* __restrict__ Wb_0, const float* __restrict__ m0,
    const float* __restrict__ W1_1, const float* __restrict__ W2_1,
    const float* __restrict__ Wa_1, const float* __restrict__ Wb_1, const float* __restrict__ m1,
    const float* __restrict__ W1_2, const float* __restrict__ W2_2,
    const float* __restrict__ Wa_2, const float* __restrict__ Wb_2, const float* __restrict__ m2)
{
    for (int i = blockIdx.x * blockDim.x + threadIdx.x; i < QTOT; i += gridDim.x * blockDim.x) {
        const float *W1, *W2, *Wa, *Wb, *m;
        int li, n, n4, in_dim, K, KW;
        if (i < QOFF1) {
            W1=W1_0; W2=W2_0; Wa=Wa_0; Wb=Wb_0; m=m0;
            li=i; n=N0; n4=NP0; in_dim=IDIM; KW=KW0;
        } else if (i < QOFF2) {
            W1=W1_1; W2=W2_1; Wa=Wa_1; Wb=Wb_1; m=m1;
            li=i-QOFF1; n=N1; n4=NP1; in_dim=N0; KW=KW1;
        } else {
            W1=W1_2; W2=W2_2; Wa=Wa_2; Wb=Wb_2; m=m2;
            li=i-QOFF2; n=N2; n4=NP2P; in_dim=N1; KW=KW2;
        }
        K = in_dim + n;
        int j = li / KW;
        int w = li - j * KW;
        int p = w >> 1, isLo = w & 1;
        int s0 = remap_k(2*p,     n, n4, in_dim);
        int s1 = remap_k(2*p + 1, n, n4, in_dim);

        float a0=0.f, a1=0.f, b0v=0.f, b1v=0.f, c0=0.f, c1=0.f;
        if (s0 >= 0) {
            int ix = j*K + s0; float mm = m[ix];
            a0 = W1[ix]*mm; b0v = W2[ix]*mm; c0 = Wa[ix] + Wb[ix];
        }
        if (s1 >= 0) {
            int ix = j*K + s1; float mm = m[ix];
            a1 = W1[ix]*mm; b1v = W2[ix]*mm; c1 = Wa[ix] + Wb[ix];
        }
        gWq1[i]  = pack_sel(a0,  a1,  isLo);
        gWq2[i]  = pack_sel(b0v, b1v, isLo);
        gWqab[i] = pack_sel(c0,  c1,  isLo);
    }
}

// h0 -> per-layer padded-row state, both parities (pad cols stay zero-init)
__global__ void init_h_kernel(const float* __restrict__ h0)
{
    for (int idx = blockIdx.x * blockDim.x + threadIdx.x; idx < BB*1024; idx += gridDim.x * blockDim.x) {
        int b = idx >> 10;
        int c = idx & 1023;
        float v = h0[idx];
        int off;
        if (c < N0)           off = OFFH0 + b * NP0 + c;
        else if (c < N0 + N1) off = OFFH1 + b * NP1 + (c - N0);
        else                  off = OFFH2 + b * NP2P + (c - N0 - N1);
        gH[0][off] = v;
        gH[1][off] = v;
    }
}

// final h: layer0 parity 1 (s=127), layer1 parity 0 (s=128), layer2 parity 1 (s=129)
__global__ void copy_hn_kernel(float* __restrict__ hn)
{
    for (int idx = blockIdx.x * blockDim.x + threadIdx.x; idx < BB*1024; idx += gridDim.x * blockDim.x) {
        int b = idx >> 10;
        int c = idx & 1023;
        float v;
        if (c < N0)           v = gH[1][OFFH0 + b * NP0 + c];
        else if (c < N0 + N1) v = gH[0][OFFH1 + b * NP1 + (c - N0)];
        else                  v = gH[1][OFFH2 + b * NP2P + (c - N0 - N1)];
        hn[idx] = v;
    }
}

// smem strides (words). Chosen for 16B alignment + conflict-free LDS.64.
#define AP 40   // As[row][k] fp32, 40 floats/row (160B)
#define WP 40   // Bs[mat][col][word], 40 words/col (160B)

// ---------------------------------------------------------------------------
// Fused CfC cell, tensor-core version. 128 threads = 4 warps.
//   BM=64 (warp w owns rows w*16..w*16+15), BN=16 (2 n8 tiles), BK=32.
//   Per k16: A frag split to bf16 hi/lo in registers; per (ntile,mat):
//   one LDS.64 per b-reg pair fetches {hi,lo} words; 3 mma per group.
// ---------------------------------------------------------------------------
template <int L>
__device__ __forceinline__ void cell_mma(
    int bidx, int t, int wp,
    const float* __restrict__ x,
    const float* __restrict__ b1, const float* __restrict__ b2,
    const float* __restrict__ ba, const float* __restrict__ bb,
    float* __restrict__ out,
    float (*As)[64][AP], uint32_t (*Bs)[3][16][WP])
{
    constexpr int n    = (L==0) ? N0 : (L==1) ? N1 : N2;
    constexpr int n4   = (L==0) ? NP0 : (L==1) ? NP1 : NP2P;
    constexpr int NT   = (L==0) ? NT0 : (L==1) ? NT1 : NT2;
    constexpr int KW   = NT * 32;
    constexpr int COLT = (L==0) ? 34 : (L==1) ? 23 : 8;
    constexpr int NPl  = n4;                                  // own-h row stride
    constexpr int NPin = (L==1) ? NP0 : (L==2) ? NP1 : 0;     // input row stride (from gH)
    constexpr int hoff = (L==0) ? OFFH0 : (L==1) ? OFFH1 : OFFH2;
    constexpr int qoff = (L==0) ? 0 : (L==1) ? QOFF1 : QOFF2;
    constexpr int ioff = (L==1) ? OFFH0 : (L==2) ? OFFH1 : 0;

    const float* prev = gH[wp ^ 1];
    const float* inA  = (L==0) ? (x + (size_t)t * IDIM) : (prev + ioff);
    const int    ldA  = (L==0) ? (TT * IDIM) : NPin;
    const float* hcur = prev + hoff;
    float*       hout = gH[wp] + hoff;

    const int tid  = threadIdx.x;
    const int lane = tid & 31;
    const int warp = tid >> 5;
    const int g    = lane >> 2;   // groupID (0..7)
    const int tig  = lane & 3;    // thread-in-group
    const int rowBase = (bidx / COLT) * 64;
    const int colBase = (bidx % COLT) * 16;

    float acc[2][3][4];
#pragma unroll
    for (int nt = 0; nt < 2; nt++)
#pragma unroll
        for (int m = 0; m < 3; m++)
#pragma unroll
            for (int q = 0; q < 4; q++) acc[nt][m][q] = 0.f;

    // ---- cp.async tile issue (A: 512 16B-chunks, W: 384) ----
    auto issue = [&](int kt, int st) {
#pragma unroll
        for (int i = 0; i < 4; i++) {
            int idx = tid + i * 128;
            int r = idx >> 3, ch = idx & 7;
            int g0 = kt * 32 + ch * 4;
            const float* src = (g0 < n4)
                ? (hcur + (size_t)(rowBase + r) * NPl + g0)
                : (inA + (size_t)(rowBase + r) * ldA + (g0 - n4));
            cp16u(&As[st][r][ch * 4], src);
        }
#pragma unroll
        for (int i = 0; i < 3; i++) {
            int idx = tid + i * 128;
            int mat = idx >> 7;            // constant per i (tid < 128)
            int r = idx & 127;
            int c = r >> 3, ch = r & 7;
            int jn = colBase + c;
            const uint32_t* src =
                ((mat == 0) ? gWq1 : (mat == 1) ? gWq2 : gWqab)
                + qoff + (size_t)(jn < n ? jn : 0) * KW + kt * 32 + ch * 4;
            cp16p(&Bs[st][mat][c][ch * 4], src, jn < n);
        }
    };

    issue(0, 0);
    cp_commit();

    for (int kt = 0; kt < NT; kt++) {
        const int st = kt & 1;
        if (kt + 1 < NT) {
            issue(kt + 1, st ^ 1);
            cp_commit();
            cp_wait<1>();
        } else {
            cp_wait<0>();
        }
        __syncthreads();

#pragma unroll
        for (int c16 = 0; c16 < 2; c16++) {
            // A fragment (16 rows x 16 k) -> bf16 hi/lo
            uint32_t ahi[4], alo[4];
            const int r0 = warp * 16 + g;
            const int kc = c16 * 16 + 2 * tig;
            float2 v;
            v = *(const float2*)&As[st][r0][kc];          split2(v.x, v.y, ahi[0], alo[0]);
            v = *(const float2*)&As[st][r0 + 8][kc];      split2(v.x, v.y, ahi[1], alo[1]);
            v = *(const float2*)&As[st][r0][kc + 8];      split2(v.x, v.y, ahi[2], alo[2]);
            v = *(const float2*)&As[st][r0 + 8][kc + 8];  split2(v.x, v.y, ahi[3], alo[3]);

#pragma unroll
            for (int nt = 0; nt < 2; nt++) {
#pragma unroll
                for (int m = 0; m < 3; m++) {
                    // b0: k-pair tig ; b1: k-pair tig+4 ; each LDS.64 -> {hi, lo}
                    uint2 w0 = *(const uint2*)&Bs[st][m][nt * 8 + g][2 * (c16 * 8 + tig)];
                    uint2 w1 = *(const uint2*)&Bs[st][m][nt * 8 + g][2 * (c16 * 8 + tig + 4)];
                    mma16816(acc[nt][m], ahi, w0.x, w1.x);
                    mma16816(acc[nt][m], ahi, w0.y, w1.y);
                    mma16816(acc[nt][m], alo, w0.x, w1.x);
                }
            }
        }
        __syncthreads();
    }

    // ---- fused CfC epilogue (C frag: rows g,g+8 ; cols 2tig,2tig+1) ----
    const int r0g = rowBase + warp * 16 + g;
#pragma unroll
    for (int nt = 0; nt < 2; nt++) {
#pragma unroll
        for (int cp = 0; cp < 2; cp++) {
            const int j = colBase + nt * 8 + 2 * tig + cp;
            if (j < n) {
                const float vb1 = b1[j], vb2 = b2[j], vbs = ba[j] + bb[j];
#pragma unroll
                for (int half = 0; half < 2; half++) {
                    const int gr = r0g + half * 8;
                    const float s1 = acc[nt][0][half * 2 + cp];
                    const float s2 = acc[nt][1][half * 2 + cp];
                    const float s3 = acc[nt][2][half * 2 + cp];
                    const float f1 = tanhf(s1 + vb1);
                    const float f2 = tanhf(s2 + vb2);
                    const float ti = 1.f / (1.f + expf(-(s3 + vbs)));
                    const float hv = f1 + ti * (f2 - f1);
                    hout[(size_t)gr * NPl + j] = hv;
                    if (L == 2) out[(size_t)gr * (TT * OUTD) + (size_t)t * OUTD + j] = hv;
                }
            }
        }
    }
}

// ---------------------------------------------------------------------------
// One wavefront: layer l active when 0 <= s-l < 128.
// ---------------------------------------------------------------------------
__global__ __launch_bounds__(128, 4) void wave_kernel(
    int s, const float* __restrict__ x,
    const float* __restrict__ b1_0, const float* __restrict__ b2_0,
    const float* __restrict__ ba_0, const float* __restrict__ bb_0,
    const float* __restrict__ b1_1, const float* __restrict__ b2_1,
    const float* __restrict__ ba_1, const float* __restrict__ bb_1,
    const float* __restrict__ b1_2, const float* __restrict__ b2_2,
    const float* __restrict__ ba_2, const float* __restrict__ bb_2,
    float* __restrict__ out)
{
    __shared__ float    As[2][64][AP];
    __shared__ uint32_t Bs[2][3][16][WP];

    const int bx = blockIdx.x;
    const int wp = s & 1;

    if (bx < BLK_L0) {
        if (s < TT)
            cell_mma<0>(bx, s, wp, x, b1_0, b2_0, ba_0, bb_0, nullptr, As, Bs);
    } else if (bx < BLK_L0 + BLK_L1) {
        int t = s - 1;
        if (t >= 0 && t < TT)
            cell_mma<1>(bx - BLK_L0, t, wp, x, b1_1, b2_1, ba_1, bb_1, nullptr, As, Bs);
    } else {
        int t = s - 2;
        if (t >= 0 && t < TT)
            cell_mma<2>(bx - BLK_L0 - BLK_L1, t, wp, x, b1_2, b2_2, ba_2, bb_2, out, As, Bs);
    }
}

// ---------------------------------------------------------------------------
// Final FC, in-place on d_out predictions region.
// ---------------------------------------------------------------------------
__global__ __launch_bounds__(256) void fc_kernel(float* __restrict__ pred,
                                                 const float* __restrict__ Wfc,
                                                 const float* __restrict__ bfc)
{
    __shared__ float As[64][129];
    const int tid  = threadIdx.x;
    const int lane = tid & 31;
    const int wrp  = tid >> 5;
    float* base = pred + (size_t)blockIdx.x * 64 * OUTD;

    for (int e = tid; e < 64 * OUTD; e += 256)
        As[e >> 7][e & 127] = base[e];
    __syncthreads();

    for (int jj = 0; jj < 16; jj++) {
        int j = jj * 8 + wrp;
        float acc0 = bfc[j], acc1 = bfc[j];
        const float* wr = Wfc + j * OUTD;
#pragma unroll 8
        for (int k = 0; k < OUTD; k++) {
            float wv = wr[k];
            acc0 += As[lane][k] * wv;
            acc1 += As[lane + 32][k] * wv;
        }
        base[lane * OUTD + j]        = acc0;
        base[(lane + 32) * OUTD + j] = acc1;
    }
}

// ---------------------------------------------------------------------------
extern "C" void kernel_launch(void* const* d_in, const int* in_sizes, int n_in,
                              void* d_out, int out_size)
{
    const float* x    = (const float*)d_in[0];
    const float* h0   = (const float*)d_in[1];

    const float* mask0 = (const float*)d_in[2];
    const float* W1_0  = (const float*)d_in[3];
    const float* W2_0  = (const float*)d_in[4];
    const float* Wa_0  = (const float*)d_in[5];
    const float* Wb_0  = (const float*)d_in[6];
    const float* b1_0  = (const float*)d_in[7];
    const float* b2_0  = (const float*)d_in[8];
    const float* ba_0  = (const float*)d_in[9];
    const float* bb_0  = (const float*)d_in[10];

    const float* mask1 = (const float*)d_in[11];
    const float* W1_1  = (const float*)d_in[12];
    const float* W2_1  = (const float*)d_in[13];
    const float* Wa_1  = (const float*)d_in[14];
    const float* Wb_1  = (const float*)d_in[15];
    const float* b1_1  = (const float*)d_in[16];
    const float* b2_1  = (const float*)d_in[17];
    const float* ba_1  = (const float*)d_in[18];
    const float* bb_1  = (const float*)d_in[19];

    const float* mask2 = (const float*)d_in[20];
    const float* W1_2  = (const float*)d_in[21];
    const float* W2_2  = (const float*)d_in[22];
    const float* Wa_2  = (const float*)d_in[23];
    const float* Wb_2  = (const float*)d_in[24];
    const float* b1_2  = (const float*)d_in[25];
    const float* b2_2  = (const float*)d_in[26];
    const float* ba_2  = (const float*)d_in[27];
    const float* bb_2  = (const float*)d_in[28];

    const float* Wfc  = (const float*)d_in[29];
    const float* bfc  = (const float*)d_in[30];

    float* out = (float*)d_out;

    prep_kernel<<<2048, 256>>>(W1_0, W2_0, Wa_0, Wb_0, mask0,
                               W1_1, W2_1, Wa_1, Wb_1, mask1,
                               W1_2, W2_2, Wa_2, Wb_2, mask2);
    init_h_kernel<<<1024, 256>>>(h0);

    // Wavefront sweep: s = 0 .. 129 (layer l computes t = s - l)
    for (int s = 0; s < TT + 2; s++) {
        wave_kernel<<<BLK_TOT, 128>>>(s, x,
                                      b1_0, b2_0, ba_0, bb_0,
                                      b1_1, b2_1, ba_1, bb_1,
                                      b1_2, b2_2, ba_2, bb_2,
                                      out);
    }

    // predictions = motor @ Wfc^T + bfc (in place)
    fc_kernel<<<(BB * TT) / 64, 256>>>(out, Wfc, bfc);

    if (out_size >= BB * TT * OUTD + BB * 1024)
        copy_hn_kernel<<<512, 256>>>(out + (size_t)BB * TT * OUTD);
}